// round 2
// baseline (speedup 1.0000x reference)
#include <cuda_runtime.h>
#include <cstdint>

#define THREADS 256
#define TILE_E  32
#define HID     128
#define KDIM    256
#define XPITCH  256

// ---- packed f32x2 helpers (Blackwell sm_103a) ----
__device__ __forceinline__ unsigned long long pack2(float a, float b) {
    unsigned long long r;
    asm("mov.b64 %0, {%1,%2};" : "=l"(r) : "f"(a), "f"(b));
    return r;
}
__device__ __forceinline__ unsigned long long dup2(float a) {
    unsigned long long r;
    asm("mov.b64 %0, {%1,%1};" : "=l"(r) : "f"(a));
    return r;
}
__device__ __forceinline__ void fma2(unsigned long long &d, unsigned long long a, unsigned long long b) {
    asm("fma.rn.f32x2 %0, %1, %2, %0;" : "+l"(d) : "l"(a), "l"(b));
}
__device__ __forceinline__ float2 unp2(unsigned long long v) {
    float lo, hi;
    asm("mov.b64 {%0,%1}, %2;" : "=f"(lo), "=f"(hi) : "l"(v));
    return make_float2(lo, hi);
}

// Fused: gather(src,dst) -> [tile,256] @ W1[256,128] + b1 -> relu -> @ W2[128,2] + b2
__global__ void __launch_bounds__(THREADS, 1)
edge_mlp_kernel(const float* __restrict__ node_emb,
                const void*  __restrict__ edge_index,
                const float* __restrict__ W1,
                const float* __restrict__ b1,
                const float* __restrict__ W2,
                const float* __restrict__ b2,
                float* __restrict__ out,
                int E)
{
    extern __shared__ float smem[];
    float* sW1  = smem;                      // [256][128] = 32768 f
    float* sX   = sW1 + KDIM * HID;          // [32][256]  = 8192 f
    float* sB1  = sX  + TILE_E * XPITCH;     // 128 f
    float* sW2  = sB1 + HID;                 // 256 f  (W2[j][c], row-major)
    int*   sIdx = (int*)(sW2 + 2 * HID);     // 64 ints

    const int tid  = threadIdx.x;
    const int warp = tid >> 5;
    const int lane = tid & 31;

    // Stage weights into SMEM (once per persistent CTA)
    for (int i = tid; i < (KDIM * HID) / 4; i += THREADS)
        ((float4*)sW1)[i] = __ldg((const float4*)W1 + i);
    if (tid < HID)     sB1[tid] = __ldg(b1 + tid);
    if (tid < 2 * HID) sW2[tid] = __ldg(W2 + tid);

    const float b2x = __ldg(b2), b2y = __ldg(b2 + 1);

    // edge_index dtype sniff: int64 values < 1e5 -> all high 32-bit words are 0.
    // For int32 data, the odd words are random indices; P(16 zeros) ~ 0.
    bool is64 = true;
    const unsigned* uw = (const unsigned*)edge_index;
    #pragma unroll
    for (int i = 0; i < 16; i++) is64 = is64 && (uw[2 * i + 1] == 0u);
    const long long* idx64 = (const long long*)edge_index;
    const int*       idx32 = (const int*)edge_index;

    const int nTiles = (E + TILE_E - 1) / TILE_E;
    float2* out2 = (float2*)out;

    for (int tile = blockIdx.x; tile < nTiles; tile += gridDim.x) {
        const int e0 = tile * TILE_E;

        __syncthreads();  // protect sX/sIdx reuse across iterations
        if (tid < 2 * TILE_E) {
            int e    = tid & (TILE_E - 1);
            int half = tid >> 5;              // 0 = src row, 1 = dst row
            int ge   = e0 + e;
            int node = 0;
            if (ge < E) {
                long long off = (long long)half * E + ge;
                node = is64 ? (int)idx64[off] : idx32[off];
            }
            sIdx[tid] = node;
        }
        __syncthreads();

        // Gather: 32 edges x (src 128f | dst 128f) = 2048 float4, L2-resident
        for (int i = tid; i < TILE_E * 64; i += THREADS) {
            int e = i >> 6, c = i & 63;
            int node = sIdx[(c >> 5) * TILE_E + e];
            float4 v = __ldg((const float4*)(node_emb + (size_t)node * HID) + (c & 31));
            ((float4*)(sX + e * XPITCH))[c] = v;
        }
        __syncthreads();

        // GEMM1: warp -> 4 edges, lane -> 4 outputs; packed f32x2 accumulators
        unsigned long long acc[4][2];
        #pragma unroll
        for (int i = 0; i < 4; i++) { acc[i][0] = 0ull; acc[i][1] = 0ull; }

        const float*  xb = sX + (warp * 4) * XPITCH;   // x broadcast within warp
        const float4* wb = (const float4*)sW1 + lane;  // conflict-free LDS.128

        #pragma unroll 4
        for (int k = 0; k < KDIM; k++) {
            float4 w = wb[k * (HID / 4)];
            unsigned long long w01 = pack2(w.x, w.y);
            unsigned long long w23 = pack2(w.z, w.w);
            #pragma unroll
            for (int i = 0; i < 4; i++) {
                unsigned long long xv = dup2(xb[i * XPITCH + k]);
                fma2(acc[i][0], xv, w01);
                fma2(acc[i][1], xv, w23);
            }
        }

        // Epilogue: +b1, ReLU, GEMM2 partials, warp-reduce over 128 outputs
        float p0[4], p1[4];
        const int j0 = lane * 4;
        #pragma unroll
        for (int i = 0; i < 4; i++) {
            float2 a = unp2(acc[i][0]), bq = unp2(acc[i][1]);
            float h[4] = {a.x, a.y, bq.x, bq.y};
            p0[i] = 0.f; p1[i] = 0.f;
            #pragma unroll
            for (int j = 0; j < 4; j++) {
                float hv = fmaxf(h[j] + sB1[j0 + j], 0.f);
                p0[i] = fmaf(hv, sW2[(j0 + j) * 2 + 0], p0[i]);
                p1[i] = fmaf(hv, sW2[(j0 + j) * 2 + 1], p1[i]);
            }
        }
        #pragma unroll
        for (int off = 16; off; off >>= 1) {
            #pragma unroll
            for (int i = 0; i < 4; i++) {
                p0[i] += __shfl_xor_sync(0xffffffffu, p0[i], off);
                p1[i] += __shfl_xor_sync(0xffffffffu, p1[i], off);
            }
        }
        if (lane == 0) {
            #pragma unroll
            for (int i = 0; i < 4; i++) {
                int e = e0 + warp * 4 + i;
                if (e < E) out2[e] = make_float2(p0[i] + b2x, p1[i] + b2y);
            }
        }
    }
}

extern "C" void kernel_launch(void* const* d_in, const int* in_sizes, int n_in,
                              void* d_out, int out_size) {
    const float* node_emb   = (const float*)d_in[0];
    const void*  edge_index = d_in[1];
    const float* W1         = (const float*)d_in[2];
    const float* b1         = (const float*)d_in[3];
    const float* W2         = (const float*)d_in[4];
    const float* b2         = (const float*)d_in[5];
    (void)in_sizes; (void)n_in;

    const int E = out_size / 2;

    const int smem_bytes = (KDIM * HID + TILE_E * XPITCH + HID + 2 * HID) * 4 + 64 * 4;
    cudaFuncSetAttribute(edge_mlp_kernel,
                         cudaFuncAttributeMaxDynamicSharedMemorySize, smem_bytes);

    int dev = 0, sms = 148;
    cudaGetDevice(&dev);
    cudaDeviceGetAttribute(&sms, cudaDevAttrMultiProcessorCount, dev);

    edge_mlp_kernel<<<sms, THREADS, smem_bytes>>>(
        node_emb, edge_index, W1, b1, W2, b2, (float*)d_out, E);
}

// round 5
// speedup vs baseline: 1.0003x; 1.0003x over previous
#include <cuda_runtime.h>
#include <cstdint>

#define THREADS 256
#define TILE_E  32
#define HID     128
#define KDIM    256
#define XPITCH  256

// ---- packed f32x2 helpers (Blackwell sm_103a) ----
__device__ __forceinline__ unsigned long long pack2(float a, float b) {
    unsigned long long r;
    asm("mov.b64 %0, {%1,%2};" : "=l"(r) : "f"(a), "f"(b));
    return r;
}
__device__ __forceinline__ unsigned long long dup2(float a) {
    unsigned long long r;
    asm("mov.b64 %0, {%1,%1};" : "=l"(r) : "f"(a));
    return r;
}
__device__ __forceinline__ void fma2(unsigned long long &d, unsigned long long a, unsigned long long b) {
    asm("fma.rn.f32x2 %0, %1, %2, %0;" : "+l"(d) : "l"(a), "l"(b));
}
__device__ __forceinline__ float2 unp2(unsigned long long v) {
    float lo, hi;
    asm("mov.b64 {%0,%1}, %2;" : "=f"(lo), "=f"(hi) : "l"(v));
    return make_float2(lo, hi);
}

// Fused: gather(src,dst) -> [tile,256] @ W1[256,128] + b1 -> relu -> @ W2[128,2] + b2
__global__ void __launch_bounds__(THREADS, 1)
edge_mlp_kernel(const float* __restrict__ node_emb,
                const void*  __restrict__ edge_index,
                const float* __restrict__ W1,
                const float* __restrict__ b1,
                const float* __restrict__ W2,
                const float* __restrict__ b2,
                float* __restrict__ out,
                int E)
{
    extern __shared__ float smem[];
    float* sW1  = smem;                      // [256][128] = 32768 f
    float* sX   = sW1 + KDIM * HID;          // [32][256]  = 8192 f
    float* sB1  = sX  + TILE_E * XPITCH;     // 128 f
    float* sW2  = sB1 + HID;                 // 256 f  (W2[j][c], row-major)
    int*   sIdx = (int*)(sW2 + 2 * HID);     // 64 ints

    const int tid  = threadIdx.x;
    const int warp = tid >> 5;
    const int lane = tid & 31;

    // Stage weights into SMEM (once per persistent CTA)
    for (int i = tid; i < (KDIM * HID) / 4; i += THREADS)
        ((float4*)sW1)[i] = __ldg((const float4*)W1 + i);
    if (tid < HID)     sB1[tid] = __ldg(b1 + tid);
    if (tid < 2 * HID) sW2[tid] = __ldg(W2 + tid);

    const float b2x = __ldg(b2), b2y = __ldg(b2 + 1);

    // edge_index dtype sniff: int64 values < 1e5 -> all high 32-bit words are 0.
    // For int32 data, the odd words are random indices; P(16 zeros) ~ 0.
    bool is64 = true;
    const unsigned* uw = (const unsigned*)edge_index;
    #pragma unroll
    for (int i = 0; i < 16; i++) is64 = is64 && (uw[2 * i + 1] == 0u);
    const long long* idx64 = (const long long*)edge_index;
    const int*       idx32 = (const int*)edge_index;

    const int nTiles = (E + TILE_E - 1) / TILE_E;
    float2* out2 = (float2*)out;

    for (int tile = blockIdx.x; tile < nTiles; tile += gridDim.x) {
        const int e0 = tile * TILE_E;

        __syncthreads();  // protect sX/sIdx reuse across iterations
        if (tid < 2 * TILE_E) {
            int e    = tid & (TILE_E - 1);
            int half = tid >> 5;              // 0 = src row, 1 = dst row
            int ge   = e0 + e;
            int node = 0;
            if (ge < E) {
                long long off = (long long)half * E + ge;
                node = is64 ? (int)idx64[off] : idx32[off];
            }
            sIdx[tid] = node;
        }
        __syncthreads();

        // Gather: 32 edges x (src 128f | dst 128f) = 2048 float4, L2-resident
        for (int i = tid; i < TILE_E * 64; i += THREADS) {
            int e = i >> 6, c = i & 63;
            int node = sIdx[(c >> 5) * TILE_E + e];
            float4 v = __ldg((const float4*)(node_emb + (size_t)node * HID) + (c & 31));
            ((float4*)(sX + e * XPITCH))[c] = v;
        }
        __syncthreads();

        // GEMM1: warp -> 4 edges, lane -> 4 outputs; packed f32x2 accumulators
        unsigned long long acc[4][2];
        #pragma unroll
        for (int i = 0; i < 4; i++) { acc[i][0] = 0ull; acc[i][1] = 0ull; }

        const float*  xb = sX + (warp * 4) * XPITCH;   // x broadcast within warp
        const float4* wb = (const float4*)sW1 + lane;  // conflict-free LDS.128

        #pragma unroll 4
        for (int k = 0; k < KDIM; k++) {
            float4 w = wb[k * (HID / 4)];
            unsigned long long w01 = pack2(w.x, w.y);
            unsigned long long w23 = pack2(w.z, w.w);
            #pragma unroll
            for (int i = 0; i < 4; i++) {
                unsigned long long xv = dup2(xb[i * XPITCH + k]);
                fma2(acc[i][0], xv, w01);
                fma2(acc[i][1], xv, w23);
            }
        }

        // Epilogue: +b1, ReLU, GEMM2 partials, warp-reduce over 128 outputs
        float p0[4], p1[4];
        const int j0 = lane * 4;
        #pragma unroll
        for (int i = 0; i < 4; i++) {
            float2 a = unp2(acc[i][0]), bq = unp2(acc[i][1]);
            float h[4] = {a.x, a.y, bq.x, bq.y};
            p0[i] = 0.f; p1[i] = 0.f;
            #pragma unroll
            for (int j = 0; j < 4; j++) {
                float hv = fmaxf(h[j] + sB1[j0 + j], 0.f);
                p0[i] = fmaf(hv, sW2[(j0 + j) * 2 + 0], p0[i]);
                p1[i] = fmaf(hv, sW2[(j0 + j) * 2 + 1], p1[i]);
            }
        }
        #pragma unroll
        for (int off = 16; off; off >>= 1) {
            #pragma unroll
            for (int i = 0; i < 4; i++) {
                p0[i] += __shfl_xor_sync(0xffffffffu, p0[i], off);
                p1[i] += __shfl_xor_sync(0xffffffffu, p1[i], off);
            }
        }
        if (lane == 0) {
            #pragma unroll
            for (int i = 0; i < 4; i++) {
                int e = e0 + warp * 4 + i;
                if (e < E) out2[e] = make_float2(p0[i] + b2x, p1[i] + b2y);
            }
        }
    }
}

extern "C" void kernel_launch(void* const* d_in, const int* in_sizes, int n_in,
                              void* d_out, int out_size) {
    const float* node_emb   = (const float*)d_in[0];
    const void*  edge_index = d_in[1];
    const float* W1         = (const float*)d_in[2];
    const float* b1         = (const float*)d_in[3];
    const float* W2         = (const float*)d_in[4];
    const float* b2         = (const float*)d_in[5];
    (void)in_sizes; (void)n_in;

    const int E = out_size / 2;

    const int smem_bytes = (KDIM * HID + TILE_E * XPITCH + HID + 2 * HID) * 4 + 64 * 4;
    cudaFuncSetAttribute(edge_mlp_kernel,
                         cudaFuncAttributeMaxDynamicSharedMemorySize, smem_bytes);

    int dev = 0, sms = 148;
    cudaGetDevice(&dev);
    cudaDeviceGetAttribute(&sms, cudaDevAttrMultiProcessorCount, dev);

    edge_mlp_kernel<<<sms, THREADS, smem_bytes>>>(
        node_emb, edge_index, W1, b1, W2, b2, (float*)d_out, E);
}

// round 9
// speedup vs baseline: 2.5015x; 2.5008x over previous
#include <cuda_runtime.h>
#include <cuda_bf16.h>
#include <cstdint>

#define HID     128
#define KDIM    256
#define TILE    64
#define THREADS 128
#define KPITCH  264      // bf16 elems per SMEM row = 528 B (16B-aligned, bank-staggered)
#define ROWB    (KPITCH * 2)

// ---- SMEM layout (bytes) ----
#define SM_B1   0
#define SM_W2   512
#define SM_WHI  2048
#define SM_WLO  (SM_WHI + HID * ROWB)          // 2048 + 67584
#define SM_XHI  (SM_WLO + HID * ROWB)          // + 67584
#define SM_XLO  (SM_XHI + TILE * ROWB)         // + 33792
#define SMEM_BYTES (SM_XLO + TILE * ROWB)      // 204800 total

#define MMA_BF16(c, a0, a1, a2, a3, b0, b1) \
    asm volatile("mma.sync.aligned.m16n8k16.row.col.f32.bf16.bf16.f32 " \
        "{%0,%1,%2,%3}, {%4,%5,%6,%7}, {%8,%9}, {%0,%1,%2,%3};" \
        : "+f"((c)[0]), "+f"((c)[1]), "+f"((c)[2]), "+f"((c)[3]) \
        : "r"(a0), "r"(a1), "r"(a2), "r"(a3), "r"(b0), "r"(b1))

#define LDSM_X4(r0, r1, r2, r3, a) \
    asm volatile("ldmatrix.sync.aligned.m8n8.x4.shared.b16 {%0,%1,%2,%3}, [%4];" \
        : "=r"(r0), "=r"(r1), "=r"(r2), "=r"(r3) : "r"(a))
#define LDSM_X2(r0, r1, a) \
    asm volatile("ldmatrix.sync.aligned.m8n8.x2.shared.b16 {%0,%1}, [%2];" \
        : "=r"(r0), "=r"(r1) : "r"(a))

static __device__ __forceinline__ uint32_t smem_u32(const void* p) {
    uint32_t a;
    asm("{ .reg .u64 t; cvta.to.shared.u64 t, %1; cvt.u32.u64 %0, t; }" : "=r"(a) : "l"(p));
    return a;
}
// pack two floats as adjacent bf16 (element 2j at low address)
static __device__ __forceinline__ uint32_t packbf(float e0, float e1) {
    union { ushort2 s; uint32_t u; } u;
    u.s.x = __bfloat16_as_ushort(__float2bfloat16(e0));
    u.s.y = __bfloat16_as_ushort(__float2bfloat16(e1));
    return u.u;
}
static __device__ __forceinline__ float bfres(float x) {
    return x - __bfloat162float(__float2bfloat16(x));
}

__global__ void __launch_bounds__(THREADS, 1)
edge_mlp_mma(const float* __restrict__ node_emb,
             const void*  __restrict__ edge_index,
             const float* __restrict__ W1,
             const float* __restrict__ b1,
             const float* __restrict__ W2,
             const float* __restrict__ b2,
             float* __restrict__ out,
             int E)
{
    extern __shared__ char smem[];
    float* sB1 = (float*)(smem + SM_B1);
    float* sW2 = (float*)(smem + SM_W2);
    const uint32_t sbase = smem_u32(smem);

    const int tid  = threadIdx.x;
    const int warp = tid >> 5;      // 4 warps x 16 edges
    const int lane = tid & 31;
    const int g    = lane >> 2;     // row group
    const int t    = lane & 3;      // thread-in-group

    // ---- one-time: b1, W2, and W1^T (hi/lo bf16, plain [n][k] rows) ----
    // NOTE: strided loops — THREADS(128) < 2*HID(256); the R7/R8 bug was
    // `if (tid < 2*HID) sW2[tid] = ...` leaving sW2[128..255] unwritten.
    for (int i = tid; i < HID;     i += THREADS) sB1[i] = __ldg(b1 + i);
    for (int i = tid; i < 2 * HID; i += THREADS) sW2[i] = __ldg(W2 + i);
    const float b2x = __ldg(b2), b2y = __ldg(b2 + 1);

    for (int i = tid; i < KDIM * HID; i += THREADS) {
        int k = i >> 7, n = i & 127;           // W1[k][n], coalesced read
        float f = __ldg(W1 + i);
        __nv_bfloat16 h = __float2bfloat16(f);
        *(__nv_bfloat16*)(smem + SM_WHI + n * ROWB + k * 2) = h;
        *(__nv_bfloat16*)(smem + SM_WLO + n * ROWB + k * 2) =
            __float2bfloat16(f - __bfloat162float(h));
    }

    // edge_index dtype sniff: int64 indices < 1e5 -> high words all zero
    bool is64 = true;
    const unsigned* uwp = (const unsigned*)edge_index;
    #pragma unroll
    for (int i = 0; i < 16; i++) is64 = is64 && (uwp[2 * i + 1] == 0u);
    const long long* idx64 = (const long long*)edge_index;
    const int*       idx32 = (const int*)edge_index;

    __syncthreads();

    // ldmatrix base addresses (advance by kt*32 bytes per K step)
    const uint32_t aHiB = sbase + SM_XHI + (uint32_t)(warp * 16 + (lane & 15)) * ROWB
                        + (uint32_t)(lane >> 4) * 16;
    const uint32_t aLoB = aHiB + (SM_XLO - SM_XHI);
    const uint32_t bHiB = sbase + SM_WHI + (uint32_t)(lane & 7) * ROWB
                        + (uint32_t)((lane >> 3) & 1) * 16;
    const uint32_t bLoB = bHiB + (SM_WLO - SM_WHI);

    const int nTiles = (E + TILE - 1) / TILE;
    float2* out2 = (float2*)out;

    for (int tile = blockIdx.x; tile < nTiles; tile += gridDim.x) {
        const int e0 = tile * TILE;

        __syncthreads();   // previous tile's X reads complete before overwrite

        // ---- gather: 2 threads per edge (src half k0-127 / dst half k128-255) ----
        {
            const int el = tid >> 1, half = tid & 1;
            const int e  = e0 + el;
            int node = 0;
            if (e < E) {
                if (is64) node = (int)idx64[half ? (size_t)E + e : (size_t)e];
                else      node = idx32[half ? (size_t)E + e : (size_t)e];
            }
            const float4* src = (const float4*)(node_emb + (size_t)node * HID);
            uint32_t* dh = (uint32_t*)(smem + SM_XHI) + el * (ROWB / 4) + half * 64;
            uint32_t* dl = (uint32_t*)(smem + SM_XLO) + el * (ROWB / 4) + half * 64;
            #pragma unroll 8
            for (int j = 0; j < 32; j++) {
                float4 v = __ldg(src + j);
                dh[2 * j]     = packbf(__bfloat162float(__float2bfloat16(v.x)),
                                       __bfloat162float(__float2bfloat16(v.y)));
                dh[2 * j + 1] = packbf(__bfloat162float(__float2bfloat16(v.z)),
                                       __bfloat162float(__float2bfloat16(v.w)));
                dl[2 * j]     = packbf(bfres(v.x), bfres(v.y));
                dl[2 * j + 1] = packbf(bfres(v.z), bfres(v.w));
            }
        }
        __syncthreads();

        // ---- MMA: warp -> 16 edges; all fragments via ldmatrix (canonical) ----
        float acc[16][4];
        #pragma unroll
        for (int nt = 0; nt < 16; nt++)
            #pragma unroll
            for (int c = 0; c < 4; c++) acc[nt][c] = 0.f;

        #pragma unroll 2
        for (int kt = 0; kt < 16; kt++) {
            uint32_t ah0, ah1, ah2, ah3, al0, al1, al2, al3;
            LDSM_X4(ah0, ah1, ah2, ah3, aHiB + kt * 32);
            LDSM_X4(al0, al1, al2, al3, aLoB + kt * 32);
            #pragma unroll
            for (int nt = 0; nt < 16; nt++) {
                uint32_t bh0, bh1, bl0, bl1;
                const uint32_t bo = (uint32_t)nt * (8 * ROWB) + (uint32_t)kt * 32;
                LDSM_X2(bh0, bh1, bHiB + bo);
                LDSM_X2(bl0, bl1, bLoB + bo);
                MMA_BF16(acc[nt], ah0, ah1, ah2, ah3, bh0, bh1);  // hi*hi
                MMA_BF16(acc[nt], al0, al1, al2, al3, bh0, bh1);  // lo*hi
                MMA_BF16(acc[nt], ah0, ah1, ah2, ah3, bl0, bl1);  // hi*lo
            }
        }

        // ---- epilogue: +b1, ReLU, x W2, quad-reduce, write ----
        float p0a = 0.f, p1a = 0.f, p0b = 0.f, p1b = 0.f;
        #pragma unroll
        for (int nt = 0; nt < 16; nt++) {
            #pragma unroll
            for (int c = 0; c < 2; c++) {
                const int f = nt * 8 + t * 2 + c;
                const float w20 = sW2[2 * f], w21 = sW2[2 * f + 1], bb = sB1[f];
                float ha = fmaxf(acc[nt][c]     + bb, 0.f);  // row g
                float hb = fmaxf(acc[nt][c + 2] + bb, 0.f);  // row g+8
                p0a = fmaf(ha, w20, p0a);  p1a = fmaf(ha, w21, p1a);
                p0b = fmaf(hb, w20, p0b);  p1b = fmaf(hb, w21, p1b);
            }
        }
        #pragma unroll
        for (int off = 1; off <= 2; off <<= 1) {
            p0a += __shfl_xor_sync(0xffffffffu, p0a, off);
            p1a += __shfl_xor_sync(0xffffffffu, p1a, off);
            p0b += __shfl_xor_sync(0xffffffffu, p0b, off);
            p1b += __shfl_xor_sync(0xffffffffu, p1b, off);
        }
        if (t == 0) {
            int ea = e0 + warp * 16 + g;
            if (ea < E)     out2[ea]     = make_float2(p0a + b2x, p1a + b2y);
            if (ea + 8 < E) out2[ea + 8] = make_float2(p0b + b2x, p1b + b2y);
        }
    }
}

extern "C" void kernel_launch(void* const* d_in, const int* in_sizes, int n_in,
                              void* d_out, int out_size) {
    const float* node_emb   = (const float*)d_in[0];
    const void*  edge_index = d_in[1];
    const float* W1         = (const float*)d_in[2];
    const float* b1         = (const float*)d_in[3];
    const float* W2         = (const float*)d_in[4];
    const float* b2         = (const float*)d_in[5];
    (void)in_sizes; (void)n_in;

    const int E = out_size / 2;
    const int nTiles = (E + TILE - 1) / TILE;

    cudaFuncSetAttribute(edge_mlp_mma,
                         cudaFuncAttributeMaxDynamicSharedMemorySize, SMEM_BYTES);

    int dev = 0, sms = 148;
    cudaGetDevice(&dev);
    cudaDeviceGetAttribute(&sms, cudaDevAttrMultiProcessorCount, dev);
    int grid = sms < nTiles ? sms : nTiles;

    edge_mlp_mma<<<grid, THREADS, SMEM_BYTES>>>(
        node_emb, edge_index, W1, b1, W2, b2, (float*)d_out, E);
}